// round 2
// baseline (speedup 1.0000x reference)
#include <cuda_runtime.h>
#include <cuda_bf16.h>

// MaskSupervisionLoss on GB300 (sm_103a).
// Inputs: pred_attn f32 (32,8,256,256), gt_masks f32 (32,8,256,256), num_objects i32 (32)
// Output: scalar f32 loss.

#define NB    32
#define NSLOT 8
#define HW    65536
#define NCH   32
#define CHUNK (HW / NCH)          // 2048 positions
#define TPB   256
#define NPOS2 (CHUNK / 2)         // 1024 float2 per chunk per slot
#define NITER (NPOS2 / TPB)       // 4 macro-iterations (2 positions each)
#define NV    66
#define EPSF  1e-6f

// value layout (per batch):
//  0: bg_inter   1: bg_psum   2: bg_gsum
//  3..9  : psum[fg 0..6]
// 10..16 : gsum[fg 0..6]
// 17..65 : inter[p][g] at 17 + p*7 + g

__device__ float g_scratch[NB * NCH * NV];

// ---------------------------------------------------------------------------
// Kernel 1: per-(batch, chunk) partial reductions via float2 streaming.
// ---------------------------------------------------------------------------
__global__ __launch_bounds__(TPB, 2)
void k_partial(const float* __restrict__ pred, const float* __restrict__ gt) {
    const int b     = blockIdx.y;
    const int chunk = blockIdx.x;

    const float2* __restrict__ pp =
        (const float2*)(pred + (size_t)b * NSLOT * HW) + chunk * NPOS2;
    const float2* __restrict__ gg =
        (const float2*)(gt   + (size_t)b * NSLOT * HW) + chunk * NPOS2;
    const int sstride = HW / 2;   // slot stride in float2

    float acc[NV];
#pragma unroll
    for (int v = 0; v < NV; v++) acc[v] = 0.f;

#pragma unroll
    for (int k = 0; k < NITER; k++) {
        const int i = k * TPB + threadIdx.x;
        float2 p2[NSLOT], g2[NSLOT];
#pragma unroll
        for (int s = 0; s < NSLOT; s++) {
            p2[s] = pp[s * sstride + i];
            g2[s] = gg[s * sstride + i];
        }
        // position 0 (.x)
        acc[0] = fmaf(p2[0].x, g2[0].x, acc[0]);
        acc[1] += p2[0].x;
        acc[2] += g2[0].x;
#pragma unroll
        for (int s = 1; s < NSLOT; s++) {
            acc[3  + s - 1] += p2[s].x;
            acc[10 + s - 1] += g2[s].x;
        }
#pragma unroll
        for (int pi = 0; pi < 7; pi++)
#pragma unroll
            for (int gi = 0; gi < 7; gi++)
                acc[17 + pi * 7 + gi] =
                    fmaf(p2[pi + 1].x, g2[gi + 1].x, acc[17 + pi * 7 + gi]);
        // position 1 (.y)
        acc[0] = fmaf(p2[0].y, g2[0].y, acc[0]);
        acc[1] += p2[0].y;
        acc[2] += g2[0].y;
#pragma unroll
        for (int s = 1; s < NSLOT; s++) {
            acc[3  + s - 1] += p2[s].y;
            acc[10 + s - 1] += g2[s].y;
        }
#pragma unroll
        for (int pi = 0; pi < 7; pi++)
#pragma unroll
            for (int gi = 0; gi < 7; gi++)
                acc[17 + pi * 7 + gi] =
                    fmaf(p2[pi + 1].y, g2[gi + 1].y, acc[17 + pi * 7 + gi]);
    }

    // warp-level tree reduce of all 66 values
#pragma unroll
    for (int v = 0; v < NV; v++) {
        float x = acc[v];
#pragma unroll
        for (int o = 16; o > 0; o >>= 1)
            x += __shfl_down_sync(0xffffffffu, x, o);
        acc[v] = x;
    }

    __shared__ float sw[TPB / 32][NV];
    const int warp = threadIdx.x >> 5;
    const int lane = threadIdx.x & 31;
    if (lane == 0) {
#pragma unroll
        for (int v = 0; v < NV; v++) sw[warp][v] = acc[v];
    }
    __syncthreads();

    if (threadIdx.x < NV) {
        float s = 0.f;
#pragma unroll
        for (int w = 0; w < TPB / 32; w++) s += sw[w][threadIdx.x];
        g_scratch[(b * NCH + chunk) * NV + threadIdx.x] = s;
    }
}

// ---------------------------------------------------------------------------
// Kernel 2 (single block): chunk reduction for all batches, dice matrices,
// optimal-assignment bitmask DP (same optimum value as Hungarian), final loss.
// ---------------------------------------------------------------------------
__global__ __launch_bounds__(TPB)
void k_finish(const int* __restrict__ nobj, float* __restrict__ out) {
    __shared__ float sm[NB][NV];
    __shared__ float sb[NB][3];   // {bg_dice, n, best_assignment_sum}

    // fixed-order sums: entry e = (b, v), sum 32 chunks
    for (int e = threadIdx.x; e < NB * NV; e += TPB) {
        const int b = e / NV, v = e % NV;
        float s = 0.f;
#pragma unroll
        for (int c = 0; c < NCH; c++)
            s += g_scratch[(b * NCH + c) * NV + v];
        sm[b][v] = s;
    }
    __syncthreads();

    // one thread per batch: dice matrix + assignment DP
    if (threadIdx.x < NB) {
        const int b = threadIdx.x;
        const float bg_dice = (2.f * sm[b][0] + EPSF) / (sm[b][1] + sm[b][2] + EPSF);

        int n = nobj[b];
        if (n > 7) n = 7;
        if (n < 0) n = 0;

        float dice[49];
#pragma unroll
        for (int p = 0; p < 7; p++)
#pragma unroll
            for (int g = 0; g < 7; g++)
                dice[p * 7 + g] = (2.f * sm[b][17 + p * 7 + g] + EPSF) /
                                  (sm[b][3 + p] + sm[b][10 + g] + EPSF);

        float Sb = 0.f;
        if (n > 0) {
            // dp[mask] = max dice-sum assigning gt cols 0..popc(mask)-1 to pred
            // rows in mask. The loss depends only on the optimal VALUE, so any
            // Hungarian tie-breaking yields the identical result.
            float dp[128];
            dp[0] = 0.f;
            for (int m = 1; m < 128; m++) {
                const int g = __popc(m) - 1;
                float best = -1e30f;
                if (g < n) {
                    for (int p = 0; p < 7; p++) {
                        if (m & (1 << p)) {
                            const float v = dp[m ^ (1 << p)] + dice[p * 7 + g];
                            if (v > best) best = v;
                        }
                    }
                }
                dp[m] = best;
            }
            Sb = -1e30f;
            for (int m = 1; m < 128; m++)
                if (__popc(m) == n && dp[m] > Sb) Sb = dp[m];
        }

        sb[b][0] = bg_dice;
        sb[b][1] = (float)n;
        sb[b][2] = Sb;
    }
    __syncthreads();

    if (threadIdx.x == 0) {
        float bg = 0.f, tot = 0.f, ssum = 0.f;
#pragma unroll
        for (int b = 0; b < NB; b++) {
            bg += 1.f - sb[b][0];
            const float n = sb[b][1];
            tot += n;
            if (n > 0.f) ssum += sb[b][2];
        }
        bg *= (1.f / (float)NB);
        const float fg = (tot > 0.f) ? (tot - ssum) / tot : 0.f;
        out[0] = bg + fg;
    }
}

// ---------------------------------------------------------------------------
extern "C" void kernel_launch(void* const* d_in, const int* in_sizes, int n_in,
                              void* d_out, int out_size) {
    const float* pred = (const float*)d_in[0];
    const float* gt   = (const float*)d_in[1];
    const int*   nobj = (const int*)d_in[2];
    float*       out  = (float*)d_out;

    dim3 grid1(NCH, NB);
    k_partial<<<grid1, TPB>>>(pred, gt);
    k_finish<<<1, TPB>>>(nobj, out);
}

// round 3
// speedup vs baseline: 1.5690x; 1.5690x over previous
#include <cuda_runtime.h>
#include <cuda_bf16.h>

// MaskSupervisionLoss on GB300 (sm_103a).
// Inputs: pred_attn f32 (32,8,256,256), gt_masks f32 (32,8,256,256), num_objects i32 (32)
// Output: scalar f32 loss.

#define NB    32
#define NSLOT 8
#define HW    65536
#define NCH   32
#define CHUNK (HW / NCH)          // 2048 positions
#define TPB   256
#define NPOS2 (CHUNK / 2)         // 1024 float2 per chunk per slot
#define NITER (NPOS2 / TPB)       // 4 macro-iterations (2 positions each)
#define NV    66
#define EPSF  1e-6f

// value layout (per batch):
//  0: bg_inter   1: bg_psum   2: bg_gsum
//  3..9  : psum[fg 0..6]
// 10..16 : gsum[fg 0..6]
// 17..65 : inter[p][g] at 17 + p*7 + g

__device__ float g_scratch[NB * NCH * NV];

// ---------------------------------------------------------------------------
// Kernel 1: per-(batch, chunk) partial reductions via float2 streaming.
// (unchanged from round 2 — measured ~27.8us, ~4.6 TB/s)
// ---------------------------------------------------------------------------
__global__ __launch_bounds__(TPB, 2)
void k_partial(const float* __restrict__ pred, const float* __restrict__ gt) {
    const int b     = blockIdx.y;
    const int chunk = blockIdx.x;

    const float2* __restrict__ pp =
        (const float2*)(pred + (size_t)b * NSLOT * HW) + chunk * NPOS2;
    const float2* __restrict__ gg =
        (const float2*)(gt   + (size_t)b * NSLOT * HW) + chunk * NPOS2;
    const int sstride = HW / 2;   // slot stride in float2

    float acc[NV];
#pragma unroll
    for (int v = 0; v < NV; v++) acc[v] = 0.f;

#pragma unroll
    for (int k = 0; k < NITER; k++) {
        const int i = k * TPB + threadIdx.x;
        float2 p2[NSLOT], g2[NSLOT];
#pragma unroll
        for (int s = 0; s < NSLOT; s++) {
            p2[s] = pp[s * sstride + i];
            g2[s] = gg[s * sstride + i];
        }
        acc[0] = fmaf(p2[0].x, g2[0].x, acc[0]);
        acc[1] += p2[0].x;
        acc[2] += g2[0].x;
#pragma unroll
        for (int s = 1; s < NSLOT; s++) {
            acc[3  + s - 1] += p2[s].x;
            acc[10 + s - 1] += g2[s].x;
        }
#pragma unroll
        for (int pi = 0; pi < 7; pi++)
#pragma unroll
            for (int gi = 0; gi < 7; gi++)
                acc[17 + pi * 7 + gi] =
                    fmaf(p2[pi + 1].x, g2[gi + 1].x, acc[17 + pi * 7 + gi]);
        acc[0] = fmaf(p2[0].y, g2[0].y, acc[0]);
        acc[1] += p2[0].y;
        acc[2] += g2[0].y;
#pragma unroll
        for (int s = 1; s < NSLOT; s++) {
            acc[3  + s - 1] += p2[s].y;
            acc[10 + s - 1] += g2[s].y;
        }
#pragma unroll
        for (int pi = 0; pi < 7; pi++)
#pragma unroll
            for (int gi = 0; gi < 7; gi++)
                acc[17 + pi * 7 + gi] =
                    fmaf(p2[pi + 1].y, g2[gi + 1].y, acc[17 + pi * 7 + gi]);
    }

#pragma unroll
    for (int v = 0; v < NV; v++) {
        float x = acc[v];
#pragma unroll
        for (int o = 16; o > 0; o >>= 1)
            x += __shfl_down_sync(0xffffffffu, x, o);
        acc[v] = x;
    }

    __shared__ float sw[TPB / 32][NV];
    const int warp = threadIdx.x >> 5;
    const int lane = threadIdx.x & 31;
    if (lane == 0) {
#pragma unroll
        for (int v = 0; v < NV; v++) sw[warp][v] = acc[v];
    }
    __syncthreads();

    if (threadIdx.x < NV) {
        float s = 0.f;
#pragma unroll
        for (int w = 0; w < TPB / 32; w++) s += sw[w][threadIdx.x];
        g_scratch[(b * NCH + chunk) * NV + threadIdx.x] = s;
    }
}

// ---------------------------------------------------------------------------
// Kernel 2 (single block, 1024 threads): chunk sums, dice matrices, and the
// optimal-assignment DP done ONE WARP PER BATCH with dp/dice in SHARED memory
// (round-2 version spilled dp[128] to local memory -> 37.7us serial chain).
// DP layers by popcount: masks within a layer are independent -> lanes work
// in parallel, __syncwarp() between layers.
// ---------------------------------------------------------------------------
__global__ __launch_bounds__(1024)
void k_finish(const int* __restrict__ nobj, float* __restrict__ out) {
    __shared__ float sm[NB][NV];        // batch sums
    __shared__ float dice[NB][49];      // dice matrices
    __shared__ float dp[NB][128];       // DP tables
    __shared__ float res[NB][3];        // {bg_dice, n, best_sum}

    const int tid = threadIdx.x;

    // fixed-order chunk sums: 2112 entries over 1024 threads
    for (int e = tid; e < NB * NV; e += 1024) {
        const int b = e / NV, v = e % NV;
        float s = 0.f;
#pragma unroll
        for (int c = 0; c < NCH; c++)
            s += g_scratch[(b * NCH + c) * NV + v];
        sm[b][v] = s;
    }
    __syncthreads();

    // dice matrices: 1568 entries
    for (int e = tid; e < NB * 49; e += 1024) {
        const int b = e / 49, idx = e % 49;
        const int p = idx / 7, g = idx % 7;
        dice[b][idx] = (2.f * sm[b][17 + idx] + EPSF) /
                       (sm[b][3 + p] + sm[b][10 + g] + EPSF);
    }
    __syncthreads();

    // one warp per batch
    const int b    = tid >> 5;
    const int lane = tid & 31;

    int n = nobj[b];
    if (n > 7) n = 7;
    if (n < 0) n = 0;

    // init dp
#pragma unroll
    for (int k = 0; k < 4; k++) dp[b][k * 32 + lane] = -1e30f;
    __syncwarp();
    if (lane == 0) dp[b][0] = 0.f;
    __syncwarp();

    // layered DP: layer L handles masks with popcount L (gt column L-1)
#pragma unroll
    for (int L = 1; L <= 7; L++) {
        const int g = L - 1;
        if (g < n) {
#pragma unroll
            for (int k = 0; k < 4; k++) {
                const int m = k * 32 + lane;
                if (__popc(m) == L) {
                    float best = -1e30f;
#pragma unroll
                    for (int p = 0; p < 7; p++) {
                        if (m & (1 << p)) {
                            const float v = dp[b][m ^ (1 << p)] + dice[b][p * 7 + g];
                            best = fmaxf(best, v);
                        }
                    }
                    dp[b][m] = best;
                }
            }
        }
        __syncwarp();
    }

    // max over masks with popcount == n
    float best = -1e30f;
    if (n > 0) {
#pragma unroll
        for (int k = 0; k < 4; k++) {
            const int m = k * 32 + lane;
            if (__popc(m) == n) best = fmaxf(best, dp[b][m]);
        }
    }
#pragma unroll
    for (int o = 16; o > 0; o >>= 1)
        best = fmaxf(best, __shfl_xor_sync(0xffffffffu, best, o));

    if (lane == 0) {
        res[b][0] = (2.f * sm[b][0] + EPSF) / (sm[b][1] + sm[b][2] + EPSF);
        res[b][1] = (float)n;
        res[b][2] = (n > 0) ? best : 0.f;
    }
    __syncthreads();

    if (tid == 0) {
        float bg = 0.f, tot = 0.f, ssum = 0.f;
#pragma unroll
        for (int bb = 0; bb < NB; bb++) {
            bg  += 1.f - res[bb][0];
            const float nn = res[bb][1];
            tot += nn;
            if (nn > 0.f) ssum += res[bb][2];
        }
        bg *= (1.f / (float)NB);
        const float fg = (tot > 0.f) ? (tot - ssum) / tot : 0.f;
        out[0] = bg + fg;
    }
}

// ---------------------------------------------------------------------------
extern "C" void kernel_launch(void* const* d_in, const int* in_sizes, int n_in,
                              void* d_out, int out_size) {
    const float* pred = (const float*)d_in[0];
    const float* gt   = (const float*)d_in[1];
    const int*   nobj = (const int*)d_in[2];
    float*       out  = (float*)d_out;

    dim3 grid1(NCH, NB);
    k_partial<<<grid1, TPB>>>(pred, gt);
    k_finish<<<1, 1024>>>(nobj, out);
}

// round 4
// speedup vs baseline: 1.6513x; 1.0525x over previous
#include <cuda_runtime.h>
#include <cuda_bf16.h>

// MaskSupervisionLoss on GB300 (sm_103a) — single fused kernel.
// Inputs: pred_attn f32 (32,8,256,256), gt_masks f32 (32,8,256,256), num_objects i32 (32)
// Output: scalar f32 loss.

#define NB    32
#define NSLOT 8
#define HW    65536
#define NCH   32
#define CHUNK (HW / NCH)          // 2048 positions
#define NPOS2 (CHUNK / 2)         // 1024 float2 per chunk per slot
#define NITER (NPOS2 / 128)       // 8 iters: each 128-thread group covers all positions
#define NV    66
#define EPSF  1e-6f

// canonical value layout (per batch):
//  0: bg_inter   1: bg_psum   2: bg_gsum
//  3..9  : psum[fg 0..6]
// 10..16 : gsum[fg 0..6]
// 17..65 : inter[p][g] at 17 + p*7 + g

__device__ float g_scratch[NB * NCH * NV];
__device__ float g_batch[NB * 3];     // {bg_dice, n, best_assignment_sum}
__device__ int   g_cnt[NB];           // zero-init; self-resetting
__device__ int   g_cnt_all;           // zero-init; self-resetting

// ---------------------------------------------------------------------------
// Fused kernel. Grid (NCH, NB), 256 threads, 3 CTAs/SM target.
// Warp-split: warps 0-3 (group A) own pred slots 0-3 + ALL gt sums;
//             warps 4-7 (group B) own pred slots 4-7 (no gt sums).
// Group A acc layout (34): 0..2 bg{inter,psum,gsum}, 3..5 psum fg0-2,
//                          6..12 gsum fg0-6, 13..33 inter rows 0-2.
// Group B acc layout (32): 0..3 psum fg3-6, 4..31 inter rows 3-6.
// ---------------------------------------------------------------------------
__global__ __launch_bounds__(256, 3)
void k_fused(const float* __restrict__ pred, const float* __restrict__ gt,
             const int* __restrict__ nobj, float* __restrict__ out) {
    const int b     = blockIdx.y;
    const int chunk = blockIdx.x;
    const int tid   = threadIdx.x;
    const int wid   = tid >> 5;
    const int lane  = tid & 31;
    const int gtid  = tid & 127;          // thread id within group
    const bool grpB = (wid >= 4);

    const float2* __restrict__ pred2 = (const float2*)pred;
    const float2* __restrict__ gt2   = (const float2*)gt;
    const size_t base = (size_t)b * NSLOT * (HW / 2) + (size_t)chunk * NPOS2;
    const int ss = HW / 2;                // slot stride in float2

    __shared__ float smA[4][34];
    __shared__ float smB[4][32];
    __shared__ int   sflag;

    if (!grpB) {
        float acc[34];
#pragma unroll
        for (int v = 0; v < 34; v++) acc[v] = 0.f;
#pragma unroll
        for (int k = 0; k < NITER; k++) {
            const int i = k * 128 + gtid;
            float2 p[4], g[8];
#pragma unroll
            for (int s = 0; s < 4; s++) p[s] = pred2[base + (size_t)s * ss + i];
#pragma unroll
            for (int s = 0; s < 8; s++) g[s] = gt2[base + (size_t)s * ss + i];
            // position .x
            acc[0] = fmaf(p[0].x, g[0].x, acc[0]);
            acc[1] += p[0].x;
            acc[2] += g[0].x;
#pragma unroll
            for (int r = 0; r < 3; r++) acc[3 + r] += p[r + 1].x;
#pragma unroll
            for (int c = 0; c < 7; c++) acc[6 + c] += g[c + 1].x;
#pragma unroll
            for (int r = 0; r < 3; r++)
#pragma unroll
                for (int c = 0; c < 7; c++)
                    acc[13 + r * 7 + c] = fmaf(p[r + 1].x, g[c + 1].x, acc[13 + r * 7 + c]);
            // position .y
            acc[0] = fmaf(p[0].y, g[0].y, acc[0]);
            acc[1] += p[0].y;
            acc[2] += g[0].y;
#pragma unroll
            for (int r = 0; r < 3; r++) acc[3 + r] += p[r + 1].y;
#pragma unroll
            for (int c = 0; c < 7; c++) acc[6 + c] += g[c + 1].y;
#pragma unroll
            for (int r = 0; r < 3; r++)
#pragma unroll
                for (int c = 0; c < 7; c++)
                    acc[13 + r * 7 + c] = fmaf(p[r + 1].y, g[c + 1].y, acc[13 + r * 7 + c]);
        }
#pragma unroll
        for (int v = 0; v < 34; v++) {
            float x = acc[v];
#pragma unroll
            for (int o = 16; o > 0; o >>= 1) x += __shfl_down_sync(0xffffffffu, x, o);
            if (lane == 0) smA[wid][v] = x;
        }
    } else {
        float acc[32];
#pragma unroll
        for (int v = 0; v < 32; v++) acc[v] = 0.f;
#pragma unroll
        for (int k = 0; k < NITER; k++) {
            const int i = k * 128 + gtid;
            float2 p[4], g[7];
#pragma unroll
            for (int s = 0; s < 4; s++) p[s] = pred2[base + (size_t)(s + 4) * ss + i];
#pragma unroll
            for (int s = 0; s < 7; s++) g[s] = gt2[base + (size_t)(s + 1) * ss + i];
            // position .x
#pragma unroll
            for (int r = 0; r < 4; r++) acc[r] += p[r].x;
#pragma unroll
            for (int r = 0; r < 4; r++)
#pragma unroll
                for (int c = 0; c < 7; c++)
                    acc[4 + r * 7 + c] = fmaf(p[r].x, g[c].x, acc[4 + r * 7 + c]);
            // position .y
#pragma unroll
            for (int r = 0; r < 4; r++) acc[r] += p[r].y;
#pragma unroll
            for (int r = 0; r < 4; r++)
#pragma unroll
                for (int c = 0; c < 7; c++)
                    acc[4 + r * 7 + c] = fmaf(p[r].y, g[c].y, acc[4 + r * 7 + c]);
        }
#pragma unroll
        for (int v = 0; v < 32; v++) {
            float x = acc[v];
#pragma unroll
            for (int o = 16; o > 0; o >>= 1) x += __shfl_down_sync(0xffffffffu, x, o);
            if (lane == 0) smB[wid - 4][v] = x;
        }
    }
    __syncthreads();

    // combine 4 warps per group, scatter to canonical layout, publish
    if (tid < 34) {
        const float s = smA[0][tid] + smA[1][tid] + smA[2][tid] + smA[3][tid];
        const int v = (tid < 6) ? tid : tid + 4;            // 6..12 -> 10..16, 13..33 -> 17..37
        g_scratch[(b * NCH + chunk) * NV + v] = s;
        __threadfence();
    } else if (tid < 66) {
        const int t = tid - 34;
        const float s = smB[0][t] + smB[1][t] + smB[2][t] + smB[3][t];
        const int v = (t < 4) ? 6 + t : t + 34;             // 0..3 -> 6..9, 4..31 -> 38..65
        g_scratch[(b * NCH + chunk) * NV + v] = s;
        __threadfence();
    }
    __syncthreads();

    if (tid == 0) sflag = (atomicAdd(&g_cnt[b], 1) == NCH - 1);
    __syncthreads();
    if (!sflag) return;

    // ================= batch finisher (last block of batch b) =================
    __shared__ float part[132];
    __shared__ float sm66[NV];
    __shared__ float dice[49];
    __shared__ float dpt[128];

    __threadfence();   // acquire side
    if (tid < 132) {
        const int v = tid >> 1, h = tid & 1;
        float s = 0.f;
#pragma unroll
        for (int c = 0; c < NCH / 2; c++)
            s += __ldcg(&g_scratch[(b * NCH + h * (NCH / 2) + c) * NV + v]);
        part[tid] = s;
    }
    __syncthreads();
    if (tid < NV) sm66[tid] = part[2 * tid] + part[2 * tid + 1];
    __syncthreads();
    if (tid < 49) {
        const int p = tid / 7, g = tid % 7;
        dice[tid] = (2.f * sm66[17 + tid] + EPSF) / (sm66[3 + p] + sm66[10 + g] + EPSF);
    }
    __syncthreads();

    if (wid == 0) {
        int n = nobj[b];
        n = (n > 7) ? 7 : (n < 0 ? 0 : n);
#pragma unroll
        for (int k = 0; k < 4; k++) dpt[k * 32 + lane] = -1e30f;
        __syncwarp();
        if (lane == 0) dpt[0] = 0.f;
        __syncwarp();
        // layered DP by popcount: optimal assignment value == Hungarian optimum
#pragma unroll
        for (int L = 1; L <= 7; L++) {
            const int g = L - 1;
            if (g < n) {
#pragma unroll
                for (int k = 0; k < 4; k++) {
                    const int m = k * 32 + lane;
                    if (__popc(m) == L) {
                        float best = -1e30f;
#pragma unroll
                        for (int p = 0; p < 7; p++)
                            if (m & (1 << p))
                                best = fmaxf(best, dpt[m ^ (1 << p)] + dice[p * 7 + g]);
                        dpt[m] = best;
                    }
                }
            }
            __syncwarp();
        }
        float best = -1e30f;
        if (n > 0) {
#pragma unroll
            for (int k = 0; k < 4; k++) {
                const int m = k * 32 + lane;
                if (__popc(m) == n) best = fmaxf(best, dpt[m]);
            }
        }
#pragma unroll
        for (int o = 16; o > 0; o >>= 1)
            best = fmaxf(best, __shfl_xor_sync(0xffffffffu, best, o));
        if (lane == 0) {
            g_batch[b * 3 + 0] = (2.f * sm66[0] + EPSF) / (sm66[1] + sm66[2] + EPSF);
            g_batch[b * 3 + 1] = (float)n;
            g_batch[b * 3 + 2] = (n > 0) ? best : 0.f;
        }
    }
    __syncthreads();

    if (tid == 0) {
        g_cnt[b] = 0;                       // reset for next graph replay
        __threadfence();
        sflag = (atomicAdd(&g_cnt_all, 1) == NB - 1);
    }
    __syncthreads();
    if (!sflag) return;

    // ================= global finisher (last batch done) =================
    if (wid == 0) {
        __threadfence();
        const float bgd = __ldcg(&g_batch[lane * 3 + 0]);
        const float nn  = __ldcg(&g_batch[lane * 3 + 1]);
        const float sv  = __ldcg(&g_batch[lane * 3 + 2]);
        float bg  = 1.f - bgd;
        float tot = nn;
        float ss  = (nn > 0.f) ? sv : 0.f;
#pragma unroll
        for (int o = 16; o > 0; o >>= 1) {
            bg  += __shfl_xor_sync(0xffffffffu, bg,  o);
            tot += __shfl_xor_sync(0xffffffffu, tot, o);
            ss  += __shfl_xor_sync(0xffffffffu, ss,  o);
        }
        if (lane == 0) {
            const float fg = (tot > 0.f) ? (tot - ss) / tot : 0.f;
            out[0] = bg * (1.f / (float)NB) + fg;
            g_cnt_all = 0;                  // reset for next graph replay
        }
    }
}

// ---------------------------------------------------------------------------
extern "C" void kernel_launch(void* const* d_in, const int* in_sizes, int n_in,
                              void* d_out, int out_size) {
    const float* pred = (const float*)d_in[0];
    const float* gt   = (const float*)d_in[1];
    const int*   nobj = (const int*)d_in[2];
    float*       out  = (float*)d_out;

    dim3 grid(NCH, NB);
    k_fused<<<grid, 256>>>(pred, gt, nobj, out);
}